// round 1
// baseline (speedup 1.0000x reference)
#include <cuda_runtime.h>
#include <cuda_bf16.h>

// Downsampler: depthwise 4x4 conv, stride 4, VALID. Non-overlapping blocks ->
// pure streaming weighted 4x4 block reduction.
// x: (16,8,1024,1024) f32, kernel: (4,4) f32, out: (16,8,256,256) f32.

#define IW 1024
#define OW 256
#define OH 256

__global__ __launch_bounds__(256) void downsample_kernel(
    const float* __restrict__ x,
    const float* __restrict__ kw,
    float* __restrict__ out)
{
    int idx = blockIdx.x * blockDim.x + threadIdx.x;
    // idx = ((nc * OH) + oy) * OW + ox
    int ox = idx & (OW - 1);
    int oy = (idx >> 8) & (OH - 1);
    int nc = idx >> 16;

    // Load 16 weights (warp-uniform, L1 broadcast)
    float k00 = __ldg(kw + 0),  k01 = __ldg(kw + 1),  k02 = __ldg(kw + 2),  k03 = __ldg(kw + 3);
    float k10 = __ldg(kw + 4),  k11 = __ldg(kw + 5),  k12 = __ldg(kw + 6),  k13 = __ldg(kw + 7);
    float k20 = __ldg(kw + 8),  k21 = __ldg(kw + 9),  k22 = __ldg(kw + 10), k23 = __ldg(kw + 11);
    float k30 = __ldg(kw + 12), k31 = __ldg(kw + 13), k32 = __ldg(kw + 14), k33 = __ldg(kw + 15);

    const float* base = x + ((size_t)nc * IW + (size_t)oy * 4) * IW + (size_t)ox * 4;

    // 4 rows x one float4 each; issue all loads up front (MLP=4)
    float4 r0 = *reinterpret_cast<const float4*>(base + 0 * IW);
    float4 r1 = *reinterpret_cast<const float4*>(base + 1 * IW);
    float4 r2 = *reinterpret_cast<const float4*>(base + 2 * IW);
    float4 r3 = *reinterpret_cast<const float4*>(base + 3 * IW);

    float acc;
    acc  = r0.x * k00 + r0.y * k01 + r0.z * k02 + r0.w * k03;
    acc += r1.x * k10 + r1.y * k11 + r1.z * k12 + r1.w * k13;
    acc += r2.x * k20 + r2.y * k21 + r2.z * k22 + r2.w * k23;
    acc += r3.x * k30 + r3.y * k31 + r3.z * k32 + r3.w * k33;

    out[idx] = acc;
}

extern "C" void kernel_launch(void* const* d_in, const int* in_sizes, int n_in,
                              void* d_out, int out_size)
{
    const float* x  = (const float*)d_in[0];
    const float* kw = (const float*)d_in[1];
    float* out = (float*)d_out;

    // total outputs = 16*8*256*256 = 8388608
    int total = out_size;           // elements
    int threads = 256;
    int blocks = (total + threads - 1) / threads;
    downsample_kernel<<<blocks, threads>>>(x, kw, out);
}

// round 2
// speedup vs baseline: 1.0470x; 1.0470x over previous
#include <cuda_runtime.h>
#include <cuda_bf16.h>

// Downsampler: depthwise 4x4 conv, stride 4, VALID -> non-overlapping weighted
// 4x4 block reduction. Pure streaming: 512MB read, 8MB write, DRAM-bound.
// R2: 2 horizontal outputs per thread -> 8 front-batched LDG.128 (MLP_p1=8),
// __ldcs streaming loads (no reuse), float2 coalesced store.

#define IW 1024
#define OW 256
#define OH 256
// outputs per thread (horizontal)
#define OPT 2

__global__ __launch_bounds__(256) void downsample_kernel(
    const float* __restrict__ x,
    const float* __restrict__ kw,
    float* __restrict__ out)
{
    int idx = blockIdx.x * blockDim.x + threadIdx.x;   // pair index
    // each thread handles outputs [2*t, 2*t+1] along ox
    int oxp = idx & (OW / OPT - 1);          // 0..127 (pair)
    int oy  = (idx >> 7) & (OH - 1);
    int nc  = idx >> 15;

    float k00 = __ldg(kw + 0),  k01 = __ldg(kw + 1),  k02 = __ldg(kw + 2),  k03 = __ldg(kw + 3);
    float k10 = __ldg(kw + 4),  k11 = __ldg(kw + 5),  k12 = __ldg(kw + 6),  k13 = __ldg(kw + 7);
    float k20 = __ldg(kw + 8),  k21 = __ldg(kw + 9),  k22 = __ldg(kw + 10), k23 = __ldg(kw + 11);
    float k30 = __ldg(kw + 12), k31 = __ldg(kw + 13), k32 = __ldg(kw + 14), k33 = __ldg(kw + 15);

    const float4* base = reinterpret_cast<const float4*>(
        x + ((size_t)nc * IW + (size_t)oy * 4) * IW) + (size_t)oxp * 2;

    // 8 streaming 128-bit loads, all issued up front (MLP=8)
    float4 a0 = __ldcs(base + 0 * (IW/4) + 0);
    float4 b0 = __ldcs(base + 0 * (IW/4) + 1);
    float4 a1 = __ldcs(base + 1 * (IW/4) + 0);
    float4 b1 = __ldcs(base + 1 * (IW/4) + 1);
    float4 a2 = __ldcs(base + 2 * (IW/4) + 0);
    float4 b2 = __ldcs(base + 2 * (IW/4) + 1);
    float4 a3 = __ldcs(base + 3 * (IW/4) + 0);
    float4 b3 = __ldcs(base + 3 * (IW/4) + 1);

    float accA, accB;
    accA  = a0.x * k00 + a0.y * k01 + a0.z * k02 + a0.w * k03;
    accA += a1.x * k10 + a1.y * k11 + a1.z * k12 + a1.w * k13;
    accA += a2.x * k20 + a2.y * k21 + a2.z * k22 + a2.w * k23;
    accA += a3.x * k30 + a3.y * k31 + a3.z * k32 + a3.w * k33;

    accB  = b0.x * k00 + b0.y * k01 + b0.z * k02 + b0.w * k03;
    accB += b1.x * k10 + b1.y * k11 + b1.z * k12 + b1.w * k13;
    accB += b2.x * k20 + b2.y * k21 + b2.z * k22 + b2.w * k23;
    accB += b3.x * k30 + b3.y * k31 + b3.z * k32 + b3.w * k33;

    float2 r;
    r.x = accA;
    r.y = accB;
    reinterpret_cast<float2*>(out)[idx] = r;
}

extern "C" void kernel_launch(void* const* d_in, const int* in_sizes, int n_in,
                              void* d_out, int out_size)
{
    const float* x  = (const float*)d_in[0];
    const float* kw = (const float*)d_in[1];
    float* out = (float*)d_out;

    int total = out_size / OPT;     // thread count (pairs)
    int threads = 256;
    int blocks = (total + threads - 1) / threads;
    downsample_kernel<<<blocks, threads>>>(x, kw, out);
}